// round 2
// baseline (speedup 1.0000x reference)
#include <cuda_runtime.h>
#include <cuda_bf16.h>
#include <math.h>

// Problem constants (fixed by reference setup_inputs)
#define BB 2
#define SS 2048
#define HH 4096
#define NQH 32
#define NKVH 8
#define DH 128
#define QKV_O 6144   // 32*128 + 8*128 + 8*128
#define Q_SIZE 4096
#define KV_SIZE 1024

// Scratch (device globals: allocation is forbidden in kernel_launch)
__device__ float g_qkv[(size_t)BB * SS * QKV_O];   // ~100 MB
__device__ float g_attn[(size_t)BB * SS * HH];     // ~67 MB

// ---------------------------------------------------------------------------
// SGEMM: C[M,N] = A[M,K] @ W[N,K]^T   (both row-major, K contiguous)
// 128x128 block tile, 256 threads (16x16), 8x8 per thread, BK=8
// ---------------------------------------------------------------------------
__global__ __launch_bounds__(256) void sgemm_nt(
    const float* __restrict__ A, const float* __restrict__ W,
    float* __restrict__ C, int M, int N, int K)
{
    __shared__ float As[8][128];
    __shared__ float Ws[8][128];

    const int tx = threadIdx.x;
    const int ty = threadIdx.y;
    const int tid = ty * 16 + tx;
    const int m0 = blockIdx.y * 128;
    const int n0 = blockIdx.x * 128;

    const int row = tid >> 1;          // 0..127
    const int kc  = (tid & 1) * 4;     // 0 or 4

    const float* Aptr = A + (size_t)(m0 + row) * K + kc;
    const float* Wptr = W + (size_t)(n0 + row) * K + kc;

    float acc[8][8];
#pragma unroll
    for (int i = 0; i < 8; i++)
#pragma unroll
        for (int j = 0; j < 8; j++) acc[i][j] = 0.f;

    for (int k0 = 0; k0 < K; k0 += 8) {
        float4 a4 = *(const float4*)(Aptr + k0);
        float4 w4 = *(const float4*)(Wptr + k0);
        __syncthreads();
        As[kc + 0][row] = a4.x; As[kc + 1][row] = a4.y;
        As[kc + 2][row] = a4.z; As[kc + 3][row] = a4.w;
        Ws[kc + 0][row] = w4.x; Ws[kc + 1][row] = w4.y;
        Ws[kc + 2][row] = w4.z; Ws[kc + 3][row] = w4.w;
        __syncthreads();
#pragma unroll
        for (int kk = 0; kk < 8; kk++) {
            float af[8], wf[8];
            *(float4*)(af)     = *(const float4*)&As[kk][ty * 8];
            *(float4*)(af + 4) = *(const float4*)&As[kk][ty * 8 + 4];
#pragma unroll
            for (int j = 0; j < 8; j++) wf[j] = Ws[kk][j * 16 + tx];
#pragma unroll
            for (int i = 0; i < 8; i++)
#pragma unroll
                for (int j = 0; j < 8; j++)
                    acc[i][j] = fmaf(af[i], wf[j], acc[i][j]);
        }
    }

#pragma unroll
    for (int i = 0; i < 8; i++) {
        size_t cb = (size_t)(m0 + ty * 8 + i) * N + n0;
#pragma unroll
        for (int j = 0; j < 8; j++)
            C[cb + j * 16 + tx] = acc[i][j];
    }
}

// ---------------------------------------------------------------------------
// RoPE (in-place on qkv): heads 0..31 = Q, 32..39 = K. One thread per (b,s,head,i<64)
// ---------------------------------------------------------------------------
__global__ void rope_kernel(float* __restrict__ qkv, const int* __restrict__ positions)
{
    int idx = blockIdx.x * blockDim.x + threadIdx.x;
    const int total = BB * SS * 40 * 64;
    if (idx >= total) return;
    int i = idx & 63;
    int t = idx >> 6;
    int head = t % 40; t /= 40;
    int s = t % SS;
    int b = t / SS;

    int pos = positions[b * SS + s];
    // inv_freq = theta^(-i/64) = 2^(-(i/64) * log2(1e6))
    float inv = exp2f(-(float)i * (19.931568569324174f / 64.0f));
    float f = (float)pos * inv;
    float sn, cs;
    sincosf(f, &sn, &cs);

    size_t base = ((size_t)(b * SS + s)) * QKV_O
                + (head < NQH ? head * DH : Q_SIZE + (head - NQH) * DH);
    float x1 = qkv[base + i];
    float x2 = qkv[base + 64 + i];
    qkv[base + i]      = x1 * cs - x2 * sn;
    qkv[base + 64 + i] = x2 * cs + x1 * sn;
}

// ---------------------------------------------------------------------------
// Flash attention (fp32, causal, GQA R=4). 64x64 tiles, D=128.
// Block: 256 threads (16x16). Thread owns 4 q-rows (ty*4+i) and
// score columns j*16+tx, output columns c*16+tx.
// ---------------------------------------------------------------------------
#define SD 132     // padded row stride for Q/K/V tiles
#define PD 68      // padded row stride for P tile
#define ATTN_SMEM ((3 * 64 * SD + 64 * PD) * 4)

__global__ __launch_bounds__(256) void attn_kernel(
    const float* __restrict__ qkv, float* __restrict__ attn_out)
{
    extern __shared__ float sm[];
    float* Qs = sm;
    float* Ks = Qs + 64 * SD;
    float* Vs = Ks + 64 * SD;
    float* Ps = Vs + 64 * SD;

    const int tx = threadIdx.x;
    const int ty = threadIdx.y;
    const int tid = ty * 16 + tx;
    const int qt = blockIdx.x;           // q tile, 0..31
    const int b  = blockIdx.y >> 5;
    const int h  = blockIdx.y & 31;
    const int g  = h >> 2;               // kv group

    const float scale = 0.08838834764831845f;  // 1/sqrt(128)

    // Load Q tile (scaled)
    {
        size_t qbase = ((size_t)(b * SS + qt * 64)) * QKV_O + h * DH;
        for (int f = tid; f < 64 * 32; f += 256) {
            int r = f >> 5;
            int c4 = (f & 31) * 4;
            float4 v = *(const float4*)&qkv[qbase + (size_t)r * QKV_O + c4];
            float* q = &Qs[r * SD + c4];
            q[0] = v.x * scale; q[1] = v.y * scale;
            q[2] = v.z * scale; q[3] = v.w * scale;
        }
    }

    float m[4], l[4], O[4][8];
#pragma unroll
    for (int i = 0; i < 4; i++) {
        m[i] = -INFINITY; l[i] = 0.f;
#pragma unroll
        for (int c = 0; c < 8; c++) O[i][c] = 0.f;
    }

    for (int kt = 0; kt <= qt; kt++) {
        size_t kbase = ((size_t)(b * SS + kt * 64)) * QKV_O + Q_SIZE + g * DH;
        size_t vbase = kbase + KV_SIZE;
        __syncthreads();   // prior iter reads of Ks/Vs/Ps done; Q stores done (kt=0)
        for (int f = tid; f < 64 * 32; f += 256) {
            int r = f >> 5;
            int c4 = (f & 31) * 4;
            float4 kv4 = *(const float4*)&qkv[kbase + (size_t)r * QKV_O + c4];
            float* kdst = &Ks[r * SD + c4];
            kdst[0] = kv4.x; kdst[1] = kv4.y; kdst[2] = kv4.z; kdst[3] = kv4.w;
            float4 vv4 = *(const float4*)&qkv[vbase + (size_t)r * QKV_O + c4];
            float* vdst = &Vs[r * SD + c4];
            vdst[0] = vv4.x; vdst[1] = vv4.y; vdst[2] = vv4.z; vdst[3] = vv4.w;
        }
        __syncthreads();

        // --- Phase A: S = Q @ K^T (Q pre-scaled) ---
        float Sf[4][4];
#pragma unroll
        for (int i = 0; i < 4; i++)
#pragma unroll
            for (int j = 0; j < 4; j++) Sf[i][j] = 0.f;

        for (int d4 = 0; d4 < DH; d4 += 4) {
            float4 qf[4], kf[4];
#pragma unroll
            for (int i = 0; i < 4; i++)
                qf[i] = *(const float4*)&Qs[(ty * 4 + i) * SD + d4];
#pragma unroll
            for (int j = 0; j < 4; j++)
                kf[j] = *(const float4*)&Ks[(j * 16 + tx) * SD + d4];
#pragma unroll
            for (int i = 0; i < 4; i++)
#pragma unroll
                for (int j = 0; j < 4; j++) {
                    Sf[i][j] = fmaf(qf[i].x, kf[j].x, Sf[i][j]);
                    Sf[i][j] = fmaf(qf[i].y, kf[j].y, Sf[i][j]);
                    Sf[i][j] = fmaf(qf[i].z, kf[j].z, Sf[i][j]);
                    Sf[i][j] = fmaf(qf[i].w, kf[j].w, Sf[i][j]);
                }
        }

        // --- causal mask (only diagonal tile) ---
        if (kt == qt) {
#pragma unroll
            for (int i = 0; i < 4; i++)
#pragma unroll
                for (int j = 0; j < 4; j++)
                    if (j * 16 + tx > ty * 4 + i) Sf[i][j] = -1e30f;
        }

        // --- online softmax update (row lives in one warp: ty pairs -> warp) ---
#pragma unroll
        for (int i = 0; i < 4; i++) {
            float lm = fmaxf(fmaxf(Sf[i][0], Sf[i][1]), fmaxf(Sf[i][2], Sf[i][3]));
#pragma unroll
            for (int o = 8; o >= 1; o >>= 1)
                lm = fmaxf(lm, __shfl_xor_sync(0xffffffffu, lm, o));
            float mn = fmaxf(m[i], lm);
            float alpha = __expf(m[i] - mn);
            float p[4], rs = 0.f;
#pragma unroll
            for (int j = 0; j < 4; j++) {
                p[j] = __expf(Sf[i][j] - mn);
                rs += p[j];
            }
#pragma unroll
            for (int o = 8; o >= 1; o >>= 1)
                rs += __shfl_xor_sync(0xffffffffu, rs, o);
            l[i] = l[i] * alpha + rs;
            m[i] = mn;
#pragma unroll
            for (int j = 0; j < 4; j++)
                Ps[(ty * 4 + i) * PD + j * 16 + tx] = p[j];
#pragma unroll
            for (int c = 0; c < 8; c++) O[i][c] *= alpha;
        }
        __syncthreads();

        // --- Phase C: O += P @ V ---
        for (int kk2 = 0; kk2 < 64; kk2++) {
            float vv[8];
#pragma unroll
            for (int c = 0; c < 8; c++)
                vv[c] = Vs[kk2 * SD + c * 16 + tx];
#pragma unroll
            for (int i = 0; i < 4; i++) {
                float p = Ps[(ty * 4 + i) * PD + kk2];
#pragma unroll
                for (int c = 0; c < 8; c++)
                    O[i][c] = fmaf(p, vv[c], O[i][c]);
            }
        }
    }

    // epilogue
#pragma unroll
    for (int i = 0; i < 4; i++) {
        float inv = 1.0f / l[i];
        size_t ob = ((size_t)(b * SS + qt * 64 + ty * 4 + i)) * HH + h * DH;
#pragma unroll
        for (int c = 0; c < 8; c++)
            attn_out[ob + c * 16 + tx] = O[i][c] * inv;
    }
}

// ---------------------------------------------------------------------------
extern "C" void kernel_launch(void* const* d_in, const int* in_sizes, int n_in,
                              void* d_out, int out_size)
{
    const float* hidden = (const float*)d_in[0];
    const int*   positions = (const int*)d_in[1];
    const float* w_qkv = (const float*)d_in[2];
    const float* w_o   = (const float*)d_in[3];
    float* out = (float*)d_out;

    float* qkv_ptr;
    float* attn_ptr;
    cudaGetSymbolAddress((void**)&qkv_ptr, g_qkv);
    cudaGetSymbolAddress((void**)&attn_ptr, g_attn);

    const int M = BB * SS;   // 4096

    // 1) QKV projection: [4096,4096] @ [6144,4096]^T -> [4096,6144]
    {
        dim3 grid(QKV_O / 128, M / 128);
        dim3 block(16, 16);
        sgemm_nt<<<grid, block>>>(hidden, w_qkv, qkv_ptr, M, QKV_O, HH);
    }

    // 2) RoPE on q and k heads
    {
        int total = BB * SS * 40 * 64;
        rope_kernel<<<(total + 255) / 256, 256>>>(qkv_ptr, positions);
    }

    // 3) Attention
    {
        cudaFuncSetAttribute(attn_kernel,
                             cudaFuncAttributeMaxDynamicSharedMemorySize, ATTN_SMEM);
        dim3 grid(SS / 64, BB * NQH);
        dim3 block(16, 16);
        attn_kernel<<<grid, block, ATTN_SMEM>>>(qkv_ptr, attn_ptr);
    }

    // 4) Output projection: [4096,4096] @ [4096,4096]^T -> [4096,4096]
    {
        dim3 grid(HH / 128, M / 128);
        dim3 block(16, 16);
        sgemm_nt<<<grid, block>>>(attn_ptr, w_o, out, M, HH, HH);
    }
}

// round 5
// speedup vs baseline: 1.3826x; 1.3826x over previous
#include <cuda_runtime.h>
#include <cuda_bf16.h>
#include <cstdint>
#include <math.h>
#include <mma.h>

using namespace nvcuda;

// Problem constants (fixed by reference setup_inputs)
#define BB 2
#define SS 2048
#define HH 4096
#define NQH 32
#define NKVH 8
#define DH 128
#define QKV_O 6144   // 32*128 + 8*128 + 8*128
#define Q_SIZE 4096
#define KV_SIZE 1024

// Scratch (device globals: allocation is forbidden in kernel_launch)
__device__ float g_qkv[(size_t)BB * SS * QKV_O];   // ~100 MB
__device__ float g_attn[(size_t)BB * SS * HH];     // ~67 MB

// ---------------------------------------------------------------------------
// TF32 tensor-core GEMM: C[M,N] = A[M,K] @ W[N,K]^T  (both row-major)
// Block tile 128x128, BK=16, 256 threads (8 warps, 2x4 warp grid, 64x32 each).
// cp.async double-buffered smem, wmma m16n16k8 tf32.
// W[N,K] row-major read as wmma col_major B with ldb = smem stride: B(k,n)=W[n,k].
// ---------------------------------------------------------------------------
#define BM 128
#define BN 128
#define BKG 16
#define LDT 20    // padded smem row stride (floats); rows mod 32 banks all distinct

__device__ __forceinline__ void cp_async16(unsigned int smem_addr, const void* gptr) {
    asm volatile("cp.async.cg.shared.global [%0], [%1], 16;\n"
                 :: "r"(smem_addr), "l"(gptr));
}
__device__ __forceinline__ unsigned int smem_u32(const void* p) {
    return (unsigned int)__cvta_generic_to_shared(p);
}

__global__ __launch_bounds__(256) void gemm_tf32(
    const float* __restrict__ A, const float* __restrict__ W,
    float* __restrict__ C, int M, int N, int K)
{
    __shared__ float sA[2][BM * LDT];
    __shared__ float sB[2][BN * LDT];

    const int tid = threadIdx.x;
    const int wid = tid >> 5;
    const int wm = wid >> 2;      // 0..1 -> 64-row slab
    const int wn = wid & 3;       // 0..3 -> 32-col slab
    const int m0 = blockIdx.y * BM;
    const int n0 = blockIdx.x * BN;

    // Global->smem mapping: per matrix per stage, 128 rows x 4 float4 = 512 chunks.
    // Thread handles chunks tid and tid+256.
    const int r0 = tid >> 2, c0 = (tid & 3) * 4;          // chunk tid
    const int r1 = (tid + 256) >> 2, c1 = ((tid + 256) & 3) * 4;

    const float* Abase = A + (size_t)m0 * K;
    const float* Wbase = W + (size_t)n0 * K;

    wmma::fragment<wmma::accumulator, 16, 16, 8, float> acc[4][2];
#pragma unroll
    for (int i = 0; i < 4; i++)
#pragma unroll
        for (int j = 0; j < 2; j++)
            wmma::fill_fragment(acc[i][j], 0.0f);

    const int NK = K / BKG;

    // Prologue: stage 0
    {
        cp_async16(smem_u32(&sA[0][r0 * LDT + c0]), Abase + (size_t)r0 * K + c0);
        cp_async16(smem_u32(&sA[0][r1 * LDT + c1]), Abase + (size_t)r1 * K + c1);
        cp_async16(smem_u32(&sB[0][r0 * LDT + c0]), Wbase + (size_t)r0 * K + c0);
        cp_async16(smem_u32(&sB[0][r1 * LDT + c1]), Wbase + (size_t)r1 * K + c1);
        asm volatile("cp.async.commit_group;");
    }

    for (int ks = 0; ks < NK; ks++) {
        if (ks + 1 < NK) {
            const int st = (ks + 1) & 1;
            const int k0 = (ks + 1) * BKG;
            cp_async16(smem_u32(&sA[st][r0 * LDT + c0]), Abase + (size_t)r0 * K + k0 + c0);
            cp_async16(smem_u32(&sA[st][r1 * LDT + c1]), Abase + (size_t)r1 * K + k0 + c1);
            cp_async16(smem_u32(&sB[st][r0 * LDT + c0]), Wbase + (size_t)r0 * K + k0 + c0);
            cp_async16(smem_u32(&sB[st][r1 * LDT + c1]), Wbase + (size_t)r1 * K + k0 + c1);
            asm volatile("cp.async.commit_group;");
            asm volatile("cp.async.wait_group 1;");
        } else {
            asm volatile("cp.async.wait_group 0;");
        }
        __syncthreads();

        const int st = ks & 1;
#pragma unroll
        for (int kk = 0; kk < BKG; kk += 8) {
            wmma::fragment<wmma::matrix_a, 16, 16, 8, wmma::precision::tf32, wmma::row_major> af[4];
            wmma::fragment<wmma::matrix_b, 16, 16, 8, wmma::precision::tf32, wmma::col_major> bf[2];
#pragma unroll
            for (int i = 0; i < 4; i++) {
                wmma::load_matrix_sync(af[i], &sA[st][(wm * 64 + i * 16) * LDT + kk], LDT);
#pragma unroll
                for (int t = 0; t < af[i].num_elements; t++)
                    af[i].x[t] = wmma::__float_to_tf32(af[i].x[t]);
            }
#pragma unroll
            for (int j = 0; j < 2; j++) {
                wmma::load_matrix_sync(bf[j], &sB[st][(wn * 32 + j * 16) * LDT + kk], LDT);
#pragma unroll
                for (int t = 0; t < bf[j].num_elements; t++)
                    bf[j].x[t] = wmma::__float_to_tf32(bf[j].x[t]);
            }
#pragma unroll
            for (int i = 0; i < 4; i++)
#pragma unroll
                for (int j = 0; j < 2; j++)
                    wmma::mma_sync(acc[i][j], af[i], bf[j], acc[i][j]);
        }
        __syncthreads();
    }

#pragma unroll
    for (int i = 0; i < 4; i++)
#pragma unroll
        for (int j = 0; j < 2; j++)
            wmma::store_matrix_sync(
                &C[(size_t)(m0 + wm * 64 + i * 16) * N + n0 + wn * 32 + j * 16],
                acc[i][j], N, wmma::mem_row_major);
}

// ---------------------------------------------------------------------------
// RoPE (in-place on qkv): heads 0..31 = Q, 32..39 = K. One thread per (b,s,head,i<64)
// ---------------------------------------------------------------------------
__global__ void rope_kernel(float* __restrict__ qkv, const int* __restrict__ positions)
{
    int idx = blockIdx.x * blockDim.x + threadIdx.x;
    const int total = BB * SS * 40 * 64;
    if (idx >= total) return;
    int i = idx & 63;
    int t = idx >> 6;
    int head = t % 40; t /= 40;
    int s = t % SS;
    int b = t / SS;

    int pos = positions[b * SS + s];
    float inv = exp2f(-(float)i * (19.931568569324174f / 64.0f));
    float f = (float)pos * inv;
    float sn, cs;
    sincosf(f, &sn, &cs);

    size_t base = ((size_t)(b * SS + s)) * QKV_O
                + (head < NQH ? head * DH : Q_SIZE + (head - NQH) * DH);
    float x1 = qkv[base + i];
    float x2 = qkv[base + 64 + i];
    qkv[base + i]      = x1 * cs - x2 * sn;
    qkv[base + 64 + i] = x2 * cs + x1 * sn;
}

// ---------------------------------------------------------------------------
// Flash attention (fp32, causal, GQA R=4). 64x64 tiles, D=128. (unchanged)
// ---------------------------------------------------------------------------
#define SD 132
#define PD 68
#define ATTN_SMEM ((3 * 64 * SD + 64 * PD) * 4)

__global__ __launch_bounds__(256) void attn_kernel(
    const float* __restrict__ qkv, float* __restrict__ attn_out)
{
    extern __shared__ float sm[];
    float* Qs = sm;
    float* Ks = Qs + 64 * SD;
    float* Vs = Ks + 64 * SD;
    float* Ps = Vs + 64 * SD;

    const int tx = threadIdx.x;
    const int ty = threadIdx.y;
    const int tid = ty * 16 + tx;
    const int qt = blockIdx.x;
    const int b  = blockIdx.y >> 5;
    const int h  = blockIdx.y & 31;
    const int g  = h >> 2;

    const float scale = 0.08838834764831845f;

    {
        size_t qbase = ((size_t)(b * SS + qt * 64)) * QKV_O + h * DH;
        for (int f = tid; f < 64 * 32; f += 256) {
            int r = f >> 5;
            int c4 = (f & 31) * 4;
            float4 v = *(const float4*)&qkv[qbase + (size_t)r * QKV_O + c4];
            float* q = &Qs[r * SD + c4];
            q[0] = v.x * scale; q[1] = v.y * scale;
            q[2] = v.z * scale; q[3] = v.w * scale;
        }
    }

    float m[4], l[4], O[4][8];
#pragma unroll
    for (int i = 0; i < 4; i++) {
        m[i] = -INFINITY; l[i] = 0.f;
#pragma unroll
        for (int c = 0; c < 8; c++) O[i][c] = 0.f;
    }

    for (int kt = 0; kt <= qt; kt++) {
        size_t kbase = ((size_t)(b * SS + kt * 64)) * QKV_O + Q_SIZE + g * DH;
        size_t vbase = kbase + KV_SIZE;
        __syncthreads();
        for (int f = tid; f < 64 * 32; f += 256) {
            int r = f >> 5;
            int c4 = (f & 31) * 4;
            float4 kv4 = *(const float4*)&qkv[kbase + (size_t)r * QKV_O + c4];
            float* kdst = &Ks[r * SD + c4];
            kdst[0] = kv4.x; kdst[1] = kv4.y; kdst[2] = kv4.z; kdst[3] = kv4.w;
            float4 vv4 = *(const float4*)&qkv[vbase + (size_t)r * QKV_O + c4];
            float* vdst = &Vs[r * SD + c4];
            vdst[0] = vv4.x; vdst[1] = vv4.y; vdst[2] = vv4.z; vdst[3] = vv4.w;
        }
        __syncthreads();

        float Sf[4][4];
#pragma unroll
        for (int i = 0; i < 4; i++)
#pragma unroll
            for (int j = 0; j < 4; j++) Sf[i][j] = 0.f;

        for (int d4 = 0; d4 < DH; d4 += 4) {
            float4 qf[4], kf[4];
#pragma unroll
            for (int i = 0; i < 4; i++)
                qf[i] = *(const float4*)&Qs[(ty * 4 + i) * SD + d4];
#pragma unroll
            for (int j = 0; j < 4; j++)
                kf[j] = *(const float4*)&Ks[(j * 16 + tx) * SD + d4];
#pragma unroll
            for (int i = 0; i < 4; i++)
#pragma unroll
                for (int j = 0; j < 4; j++) {
                    Sf[i][j] = fmaf(qf[i].x, kf[j].x, Sf[i][j]);
                    Sf[i][j] = fmaf(qf[i].y, kf[j].y, Sf[i][j]);
                    Sf[i][j] = fmaf(qf[i].z, kf[j].z, Sf[i][j]);
                    Sf[i][j] = fmaf(qf[i].w, kf[j].w, Sf[i][j]);
                }
        }

        if (kt == qt) {
#pragma unroll
            for (int i = 0; i < 4; i++)
#pragma unroll
                for (int j = 0; j < 4; j++)
                    if (j * 16 + tx > ty * 4 + i) Sf[i][j] = -1e30f;
        }

#pragma unroll
        for (int i = 0; i < 4; i++) {
            float lm = fmaxf(fmaxf(Sf[i][0], Sf[i][1]), fmaxf(Sf[i][2], Sf[i][3]));
#pragma unroll
            for (int o = 8; o >= 1; o >>= 1)
                lm = fmaxf(lm, __shfl_xor_sync(0xffffffffu, lm, o));
            float mn = fmaxf(m[i], lm);
            float alpha = __expf(m[i] - mn);
            float p[4], rs = 0.f;
#pragma unroll
            for (int j = 0; j < 4; j++) {
                p[j] = __expf(Sf[i][j] - mn);
                rs += p[j];
            }
#pragma unroll
            for (int o = 8; o >= 1; o >>= 1)
                rs += __shfl_xor_sync(0xffffffffu, rs, o);
            l[i] = l[i] * alpha + rs;
            m[i] = mn;
#pragma unroll
            for (int j = 0; j < 4; j++)
                Ps[(ty * 4 + i) * PD + j * 16 + tx] = p[j];
#pragma unroll
            for (int c = 0; c < 8; c++) O[i][c] *= alpha;
        }
        __syncthreads();

        for (int kk2 = 0; kk2 < 64; kk2++) {
            float vv[8];
#pragma unroll
            for (int c = 0; c < 8; c++)
                vv[c] = Vs[kk2 * SD + c * 16 + tx];
#pragma unroll
            for (int i = 0; i < 4; i++) {
                float p = Ps[(ty * 4 + i) * PD + kk2];
#pragma unroll
                for (int c = 0; c < 8; c++)
                    O[i][c] = fmaf(p, vv[c], O[i][c]);
            }
        }
    }

#pragma unroll
    for (int i = 0; i < 4; i++) {
        float inv = 1.0f / l[i];
        size_t ob = ((size_t)(b * SS + qt * 64 + ty * 4 + i)) * HH + h * DH;
#pragma unroll
        for (int c = 0; c < 8; c++)
            attn_out[ob + c * 16 + tx] = O[i][c] * inv;
    }
}

// ---------------------------------------------------------------------------
extern "C" void kernel_launch(void* const* d_in, const int* in_sizes, int n_in,
                              void* d_out, int out_size)
{
    const float* hidden = (const float*)d_in[0];
    const int*   positions = (const int*)d_in[1];
    const float* w_qkv = (const float*)d_in[2];
    const float* w_o   = (const float*)d_in[3];
    float* out = (float*)d_out;

    float* qkv_ptr;
    float* attn_ptr;
    cudaGetSymbolAddress((void**)&qkv_ptr, g_qkv);
    cudaGetSymbolAddress((void**)&attn_ptr, g_attn);

    const int M = BB * SS;   // 4096

    // 1) QKV projection: [4096,4096] @ [6144,4096]^T -> [4096,6144]  (TF32 TC)
    {
        dim3 grid(QKV_O / BN, M / BM);
        gemm_tf32<<<grid, 256>>>(hidden, w_qkv, qkv_ptr, M, QKV_O, HH);
    }

    // 2) RoPE on q and k heads
    {
        int total = BB * SS * 40 * 64;
        rope_kernel<<<(total + 255) / 256, 256>>>(qkv_ptr, positions);
    }

    // 3) Attention
    {
        cudaFuncSetAttribute(attn_kernel,
                             cudaFuncAttributeMaxDynamicSharedMemorySize, ATTN_SMEM);
        dim3 grid(SS / 64, BB * NQH);
        dim3 block(16, 16);
        attn_kernel<<<grid, block, ATTN_SMEM>>>(qkv_ptr, attn_ptr);
    }

    // 4) Output projection: [4096,4096] @ [4096,4096]^T -> [4096,4096]  (TF32 TC)
    {
        dim3 grid(HH / BN, M / BM);
        gemm_tf32<<<grid, 256>>>(attn_ptr, w_o, out, M, HH, HH);
    }
}

// round 6
// speedup vs baseline: 1.4404x; 1.0417x over previous
#include <cuda_runtime.h>
#include <cuda_bf16.h>
#include <cstdint>
#include <math.h>
#include <mma.h>

using namespace nvcuda;

// Problem constants (fixed by reference setup_inputs)
#define BB 2
#define SS 2048
#define HH 4096
#define NQH 32
#define NKVH 8
#define DH 128
#define QKV_O 6144   // 32*128 + 8*128 + 8*128
#define Q_SIZE 4096
#define KV_SIZE 1024

__device__ float g_qkv[(size_t)BB * SS * QKV_O];   // ~100 MB
__device__ float g_attn[(size_t)BB * SS * HH];     // ~67 MB

// ---------------------------------------------------------------------------
// TF32 tensor-core GEMM (unchanged from R5): C[M,N] = A[M,K] @ W[N,K]^T
// ---------------------------------------------------------------------------
#define BM 128
#define BN 128
#define BKG 16
#define LDT 20

__device__ __forceinline__ void cp_async16(unsigned int smem_addr, const void* gptr) {
    asm volatile("cp.async.cg.shared.global [%0], [%1], 16;\n"
                 :: "r"(smem_addr), "l"(gptr));
}
__device__ __forceinline__ unsigned int smem_u32(const void* p) {
    return (unsigned int)__cvta_generic_to_shared(p);
}

__global__ __launch_bounds__(256) void gemm_tf32(
    const float* __restrict__ A, const float* __restrict__ W,
    float* __restrict__ C, int M, int N, int K)
{
    __shared__ float sA[2][BM * LDT];
    __shared__ float sB[2][BN * LDT];

    const int tid = threadIdx.x;
    const int wid = tid >> 5;
    const int wm = wid >> 2;
    const int wn = wid & 3;
    const int m0 = blockIdx.y * BM;
    const int n0 = blockIdx.x * BN;

    const int r0 = tid >> 2, c0 = (tid & 3) * 4;
    const int r1 = (tid + 256) >> 2, c1 = ((tid + 256) & 3) * 4;

    const float* Abase = A + (size_t)m0 * K;
    const float* Wbase = W + (size_t)n0 * K;

    wmma::fragment<wmma::accumulator, 16, 16, 8, float> acc[4][2];
#pragma unroll
    for (int i = 0; i < 4; i++)
#pragma unroll
        for (int j = 0; j < 2; j++)
            wmma::fill_fragment(acc[i][j], 0.0f);

    const int NK = K / BKG;

    {
        cp_async16(smem_u32(&sA[0][r0 * LDT + c0]), Abase + (size_t)r0 * K + c0);
        cp_async16(smem_u32(&sA[0][r1 * LDT + c1]), Abase + (size_t)r1 * K + c1);
        cp_async16(smem_u32(&sB[0][r0 * LDT + c0]), Wbase + (size_t)r0 * K + c0);
        cp_async16(smem_u32(&sB[0][r1 * LDT + c1]), Wbase + (size_t)r1 * K + c1);
        asm volatile("cp.async.commit_group;");
    }

    for (int ks = 0; ks < NK; ks++) {
        if (ks + 1 < NK) {
            const int st = (ks + 1) & 1;
            const int k0 = (ks + 1) * BKG;
            cp_async16(smem_u32(&sA[st][r0 * LDT + c0]), Abase + (size_t)r0 * K + k0 + c0);
            cp_async16(smem_u32(&sA[st][r1 * LDT + c1]), Abase + (size_t)r1 * K + k0 + c1);
            cp_async16(smem_u32(&sB[st][r0 * LDT + c0]), Wbase + (size_t)r0 * K + k0 + c0);
            cp_async16(smem_u32(&sB[st][r1 * LDT + c1]), Wbase + (size_t)r1 * K + k0 + c1);
            asm volatile("cp.async.commit_group;");
            asm volatile("cp.async.wait_group 1;");
        } else {
            asm volatile("cp.async.wait_group 0;");
        }
        __syncthreads();

        const int st = ks & 1;
#pragma unroll
        for (int kk = 0; kk < BKG; kk += 8) {
            wmma::fragment<wmma::matrix_a, 16, 16, 8, wmma::precision::tf32, wmma::row_major> af[4];
            wmma::fragment<wmma::matrix_b, 16, 16, 8, wmma::precision::tf32, wmma::col_major> bf[2];
#pragma unroll
            for (int i = 0; i < 4; i++) {
                wmma::load_matrix_sync(af[i], &sA[st][(wm * 64 + i * 16) * LDT + kk], LDT);
#pragma unroll
                for (int t = 0; t < af[i].num_elements; t++)
                    af[i].x[t] = wmma::__float_to_tf32(af[i].x[t]);
            }
#pragma unroll
            for (int j = 0; j < 2; j++) {
                wmma::load_matrix_sync(bf[j], &sB[st][(wn * 32 + j * 16) * LDT + kk], LDT);
#pragma unroll
                for (int t = 0; t < bf[j].num_elements; t++)
                    bf[j].x[t] = wmma::__float_to_tf32(bf[j].x[t]);
            }
#pragma unroll
            for (int i = 0; i < 4; i++)
#pragma unroll
                for (int j = 0; j < 2; j++)
                    wmma::mma_sync(acc[i][j], af[i], bf[j], acc[i][j]);
        }
        __syncthreads();
    }

#pragma unroll
    for (int i = 0; i < 4; i++)
#pragma unroll
        for (int j = 0; j < 2; j++)
            wmma::store_matrix_sync(
                &C[(size_t)(m0 + wm * 64 + i * 16) * N + n0 + wn * 32 + j * 16],
                acc[i][j], N, wmma::mem_row_major);
}

// ---------------------------------------------------------------------------
// RoPE (unchanged)
// ---------------------------------------------------------------------------
__global__ void rope_kernel(float* __restrict__ qkv, const int* __restrict__ positions)
{
    int idx = blockIdx.x * blockDim.x + threadIdx.x;
    const int total = BB * SS * 40 * 64;
    if (idx >= total) return;
    int i = idx & 63;
    int t = idx >> 6;
    int head = t % 40; t /= 40;
    int s = t % SS;
    int b = t / SS;

    int pos = positions[b * SS + s];
    float inv = exp2f(-(float)i * (19.931568569324174f / 64.0f));
    float f = (float)pos * inv;
    float sn, cs;
    sincosf(f, &sn, &cs);

    size_t base = ((size_t)(b * SS + s)) * QKV_O
                + (head < NQH ? head * DH : Q_SIZE + (head - NQH) * DH);
    float x1 = qkv[base + i];
    float x2 = qkv[base + 64 + i];
    qkv[base + i]      = x1 * cs - x2 * sn;
    qkv[base + 64 + i] = x2 * cs + x1 * sn;
}

// ---------------------------------------------------------------------------
// Flash attention with TF32 tensor cores.
// Block 256 threads (8 warps), tile 64 q-rows x 64 k-cols, D=128.
// Warp grid for S (64x64): warp_m = wid>>1 (4), warp_n = wid&1 (2 x 32 cols).
// Warp grid for PV (64x128): same rows, warp_n covers 64 cols (4 frags).
// Softmax + online rescale done scalar via smem round-trip:
//   thread owns row r = tid>>2, col-part = tid&3 (16 cols for softmax,
//   8 float4 chunks for O accumulation).
// ---------------------------------------------------------------------------
#define SD 132     // Q/K/V/Ot row stride (floats)
#define SSD 68     // S/P row stride
// floats: 3*64*SD + 64*SSD + 64*SD + 64  = 4*8448 + 4352 + 64
#define ATTN_SMEM ((4 * 64 * SD + 64 * SSD + 64) * 4)

__global__ __launch_bounds__(256) void attn_tc(
    const float* __restrict__ qkv, float* __restrict__ attn_out)
{
    extern __shared__ float sm[];
    float* Qs = sm;                    // 64 x SD
    float* Ks = Qs + 64 * SD;          // 64 x SD
    float* Vs = Ks + 64 * SD;          // 64 x SD
    float* Ot = Vs + 64 * SD;          // 64 x SD (PV tile, 128 cols used)
    float* Ss = Ot + 64 * SD;          // 64 x SSD (scores, then P)
    float* salpha = Ss + 64 * SSD;     // 64

    const int tid = threadIdx.x;
    const int wid = tid >> 5;
    const int warp_m = wid >> 1;       // 0..3 -> 16-row slab
    const int warp_n = wid & 1;        // 0..1
    const int qt = blockIdx.x;
    const int b  = blockIdx.y >> 5;
    const int h  = blockIdx.y & 31;
    const int g  = h >> 2;

    const float scale = 0.08838834764831845f;  // 1/sqrt(128)

    // softmax/O ownership
    const int r = tid >> 2;            // 0..63
    const int part = tid & 3;

    // Load Q tile (scaled)
    {
        size_t qbase = ((size_t)(b * SS + qt * 64)) * QKV_O + h * DH;
        for (int f = tid; f < 64 * 32; f += 256) {
            int rr = f >> 5;
            int c4 = (f & 31) * 4;
            float4 v = *(const float4*)&qkv[qbase + (size_t)rr * QKV_O + c4];
            float* q = &Qs[rr * SD + c4];
            q[0] = v.x * scale; q[1] = v.y * scale;
            q[2] = v.z * scale; q[3] = v.w * scale;
        }
    }

    float m_r = -INFINITY, l_r = 0.f;
    float O_r[32];                     // chunk i -> cols (part + 4*i)*4 .. +3
#pragma unroll
    for (int i = 0; i < 32; i++) O_r[i] = 0.f;

    for (int kt = 0; kt <= qt; kt++) {
        __syncthreads();   // prior iter consumed Ks/Vs/Ot/Ss; Q ready (kt=0)
        {
            size_t kbase = ((size_t)(b * SS + kt * 64)) * QKV_O + Q_SIZE + g * DH;
            size_t vbase = kbase + KV_SIZE;
            for (int f = tid; f < 64 * 32; f += 256) {
                int rr = f >> 5;
                int c4 = (f & 31) * 4;
                float4 kv4 = *(const float4*)&qkv[kbase + (size_t)rr * QKV_O + c4];
                float* kdst = &Ks[rr * SD + c4];
                kdst[0] = kv4.x; kdst[1] = kv4.y; kdst[2] = kv4.z; kdst[3] = kv4.w;
                float4 vv4 = *(const float4*)&qkv[vbase + (size_t)rr * QKV_O + c4];
                float* vdst = &Vs[rr * SD + c4];
                vdst[0] = vv4.x; vdst[1] = vv4.y; vdst[2] = vv4.z; vdst[3] = vv4.w;
            }
        }
        __syncthreads();

        // --- S = Q @ K^T via wmma tf32: each warp 16 rows x 32 cols ---
        {
            wmma::fragment<wmma::accumulator, 16, 16, 8, float> accS[2];
#pragma unroll
            for (int j = 0; j < 2; j++) wmma::fill_fragment(accS[j], 0.0f);

#pragma unroll
            for (int kk = 0; kk < DH; kk += 8) {
                wmma::fragment<wmma::matrix_a, 16, 16, 8, wmma::precision::tf32, wmma::row_major> af;
                wmma::load_matrix_sync(af, &Qs[(warp_m * 16) * SD + kk], SD);
#pragma unroll
                for (int t = 0; t < af.num_elements; t++)
                    af.x[t] = wmma::__float_to_tf32(af.x[t]);
#pragma unroll
                for (int j = 0; j < 2; j++) {
                    wmma::fragment<wmma::matrix_b, 16, 16, 8, wmma::precision::tf32, wmma::col_major> bf;
                    wmma::load_matrix_sync(bf, &Ks[(warp_n * 32 + j * 16) * SD + kk], SD);
#pragma unroll
                    for (int t = 0; t < bf.num_elements; t++)
                        bf.x[t] = wmma::__float_to_tf32(bf.x[t]);
                    wmma::mma_sync(accS[j], af, bf, accS[j]);
                }
            }
#pragma unroll
            for (int j = 0; j < 2; j++)
                wmma::store_matrix_sync(&Ss[(warp_m * 16) * SSD + warp_n * 32 + j * 16],
                                        accS[j], SSD, wmma::mem_row_major);
        }
        __syncthreads();

        // --- scalar online softmax: row r, cols part*16 .. part*16+15 ---
        {
            const int cbase = part * 16;
            float sv[16];
            float lm = -INFINITY;
#pragma unroll
            for (int j = 0; j < 16; j++) {
                float s = Ss[r * SSD + cbase + j];
                if (kt == qt && (cbase + j) > r) s = -1e30f;
                sv[j] = s;
                lm = fmaxf(lm, s);
            }
            lm = fmaxf(lm, __shfl_xor_sync(0xffffffffu, lm, 1));
            lm = fmaxf(lm, __shfl_xor_sync(0xffffffffu, lm, 2));
            float mn = fmaxf(m_r, lm);
            float alpha = __expf(m_r - mn);
            float rs = 0.f;
#pragma unroll
            for (int j = 0; j < 16; j++) {
                float p = __expf(sv[j] - mn);
                Ss[r * SSD + cbase + j] = p;
                rs += p;
            }
            rs += __shfl_xor_sync(0xffffffffu, rs, 1);
            rs += __shfl_xor_sync(0xffffffffu, rs, 2);
            l_r = l_r * alpha + rs;
            m_r = mn;
            if (part == 0) salpha[r] = alpha;
        }
        __syncthreads();

        // --- PV = P @ V via wmma tf32: each warp 16 rows x 64 cols ---
        {
            wmma::fragment<wmma::accumulator, 16, 16, 8, float> accO[4];
#pragma unroll
            for (int j = 0; j < 4; j++) wmma::fill_fragment(accO[j], 0.0f);

#pragma unroll
            for (int kk = 0; kk < 64; kk += 8) {
                wmma::fragment<wmma::matrix_a, 16, 16, 8, wmma::precision::tf32, wmma::row_major> af;
                wmma::load_matrix_sync(af, &Ss[(warp_m * 16) * SSD + kk], SSD);
#pragma unroll
                for (int t = 0; t < af.num_elements; t++)
                    af.x[t] = wmma::__float_to_tf32(af.x[t]);
#pragma unroll
                for (int j = 0; j < 4; j++) {
                    wmma::fragment<wmma::matrix_b, 16, 16, 8, wmma::precision::tf32, wmma::row_major> bf;
                    wmma::load_matrix_sync(bf, &Vs[kk * SD + warp_n * 64 + j * 16], SD);
#pragma unroll
                    for (int t = 0; t < bf.num_elements; t++)
                        bf.x[t] = wmma::__float_to_tf32(bf.x[t]);
                    wmma::mma_sync(accO[j], af, bf, accO[j]);
                }
            }
#pragma unroll
            for (int j = 0; j < 4; j++)
                wmma::store_matrix_sync(&Ot[(warp_m * 16) * SD + warp_n * 64 + j * 16],
                                        accO[j], SD, wmma::mem_row_major);
        }
        __syncthreads();

        // --- O update: O = O*alpha + Ot (thread owns row r, chunks part+4i) ---
        {
            float alpha_r = salpha[r];
#pragma unroll
            for (int i = 0; i < 8; i++) {
                float4 t4 = *(const float4*)&Ot[r * SD + (part + 4 * i) * 4];
                O_r[4 * i + 0] = O_r[4 * i + 0] * alpha_r + t4.x;
                O_r[4 * i + 1] = O_r[4 * i + 1] * alpha_r + t4.y;
                O_r[4 * i + 2] = O_r[4 * i + 2] * alpha_r + t4.z;
                O_r[4 * i + 3] = O_r[4 * i + 3] * alpha_r + t4.w;
            }
        }
    }

    // epilogue
    {
        float inv = 1.0f / l_r;
        size_t ob = ((size_t)(b * SS + qt * 64 + r)) * HH + h * DH;
#pragma unroll
        for (int i = 0; i < 8; i++) {
            float4 o4;
            o4.x = O_r[4 * i + 0] * inv;
            o4.y = O_r[4 * i + 1] * inv;
            o4.z = O_r[4 * i + 2] * inv;
            o4.w = O_r[4 * i + 3] * inv;
            *(float4*)&attn_out[ob + (part + 4 * i) * 4] = o4;
        }
    }
}

// ---------------------------------------------------------------------------
extern "C" void kernel_launch(void* const* d_in, const int* in_sizes, int n_in,
                              void* d_out, int out_size)
{
    const float* hidden = (const float*)d_in[0];
    const int*   positions = (const int*)d_in[1];
    const float* w_qkv = (const float*)d_in[2];
    const float* w_o   = (const float*)d_in[3];
    float* out = (float*)d_out;

    float* qkv_ptr;
    float* attn_ptr;
    cudaGetSymbolAddress((void**)&qkv_ptr, g_qkv);
    cudaGetSymbolAddress((void**)&attn_ptr, g_attn);

    const int M = BB * SS;   // 4096

    // 1) QKV projection (TF32 TC)
    {
        dim3 grid(QKV_O / BN, M / BM);
        gemm_tf32<<<grid, 256>>>(hidden, w_qkv, qkv_ptr, M, QKV_O, HH);
    }

    // 2) RoPE
    {
        int total = BB * SS * 40 * 64;
        rope_kernel<<<(total + 255) / 256, 256>>>(qkv_ptr, positions);
    }

    // 3) Attention (TF32 TC)
    {
        cudaFuncSetAttribute(attn_tc,
                             cudaFuncAttributeMaxDynamicSharedMemorySize, ATTN_SMEM);
        dim3 grid(SS / 64, BB * NQH);
        attn_tc<<<grid, 256, ATTN_SMEM>>>(qkv_ptr, attn_ptr);
    }

    // 4) Output projection (TF32 TC)
    {
        dim3 grid(HH / BN, M / BM);
        gemm_tf32<<<grid, 256>>>(attn_ptr, w_o, out, M, HH, HH);
    }
}